// round 13
// baseline (speedup 1.0000x reference)
#include <cuda_runtime.h>
#include <cstring>
#include <cstdint>

#define RS2 0.7071067811865476f
#define TAU_V 0.05f

constexpr int SH  = 34;             // float strides, even
constexpr int SD  = 1090;
constexpr int SH2 = 17;             // float2 strides
constexpr int SD2 = 545;
constexpr int HALF_F2 = 16 * SD2;   // 8720 float2 = half tile (16 d-slots)
constexpr int SSH = 18, SSD = 290;  // scratch float strides
constexpr int SSH2 = 9, SSD2 = 145; // scratch float2 strides
constexpr int SCR_F2 = 16 * SSD2;   // 2320 float2
constexpr int NT = 256;
// smem bytes = (8720 + 2320) * 8 = 88320

// 28 level-1 blocks per CTA: e = p*16 + bh8*4 + bw8, excluding p==0 && bh8<2 && bw8<2
__device__ __constant__ unsigned char BTAB[28] = {
    2,3,6,7,8,9,10,11,12,13,14,15,
    16,17,18,19,20,21,22,23,24,25,26,27,28,29,30,31};

extern __shared__ float2 smem2[];

__device__ __forceinline__ float2 f2add(float2 a, float2 b) {
    return make_float2((a.x + b.x) * RS2, (a.y + b.y) * RS2);
}
__device__ __forceinline__ float2 f2sub(float2 a, float2 b) {
    return make_float2((a.x - b.x) * RS2, (a.y - b.y) * RS2);
}

__device__ __forceinline__ uint32_t smem_u32(const void* p) {
    uint32_t a;
    asm("{ .reg .u64 t; cvta.to.shared.u64 t, %1; cvt.u32.u64 %0, t; }" : "=r"(a) : "l"(p));
    return a;
}
__device__ __forceinline__ float2 peer_ld_f2(uint32_t laddr, uint32_t prank) {
    uint32_t ra;
    asm("mapa.shared::cluster.u32 %0, %1, %2;" : "=r"(ra) : "r"(laddr), "r"(prank));
    unsigned long long u;
    asm volatile("ld.shared::cluster.b64 %0, [%1];" : "=l"(u) : "r"(ra));
    float2 v; memcpy(&v, &u, 8);
    return v;
}
__device__ __forceinline__ void cluster_sync() {
    asm volatile("barrier.cluster.arrive.aligned;" ::: "memory");
    asm volatile("barrier.cluster.wait.aligned;" ::: "memory");
}

// in-place float2 Haar line transform along stride SL2 (compacted lo/hi halves)
template<int N, int SL2, bool FWD>
__device__ __forceinline__ void line_f2(float2* p) {
    float2 v[N];
#pragma unroll
    for (int k = 0; k < N; k++) v[k] = p[k * SL2];
#pragma unroll
    for (int i = 0; i < N / 2; i++) {
        if (FWD) {
            p[i * SL2]           = f2add(v[2*i], v[2*i+1]);
            p[(i + N/2) * SL2]   = f2sub(v[2*i], v[2*i+1]);
        } else {
            p[(2*i) * SL2]       = f2add(v[i], v[i + N/2]);
            p[(2*i + 1) * SL2]   = f2sub(v[i], v[i + N/2]);
        }
    }
}

// level-1 d butterfly on 16 local slots, INTERLEAVED in place (self-inverse form):
// (slot2i, slot2i+1) -> ((a+b)*r, (a-b)*r). Same op is fwd (x->lo,hi) and inv (lo,hi->even,odd).
__device__ __forceinline__ void dpassD(float2* T2, int tid) {
    for (int c = tid; c < 512; c += NT) {
        int h = c >> 4, wp = c & 15;
        float2* p = T2 + h * SH2 + wp;
        float2 v[16];
#pragma unroll
        for (int k = 0; k < 16; k++) v[k] = p[k * SD2];
#pragma unroll
        for (int i = 0; i < 8; i++) {
            p[(2*i)   * SD2] = f2add(v[2*i], v[2*i+1]);
            p[(2*i+1) * SD2] = f2sub(v[2*i], v[2*i+1]);
        }
    }
}

// scratch (16^3 lll) passes
template<bool FWD>
__device__ __forceinline__ void scr_w(float2* S2, int tid) {
    int d = tid >> 4, h = tid & 15;
    float2* p = S2 + d * SSD2 + h * SSH2;
    float2 q[8];
#pragma unroll
    for (int k = 0; k < 8; k++) q[k] = p[k];
    if (FWD) {
#pragma unroll
        for (int t = 0; t < 4; t++) {
            float2 lo, hi;
            lo.x = (q[2*t].x   + q[2*t].y)   * RS2;
            lo.y = (q[2*t+1].x + q[2*t+1].y) * RS2;
            hi.x = (q[2*t].x   - q[2*t].y)   * RS2;
            hi.y = (q[2*t+1].x - q[2*t+1].y) * RS2;
            p[t] = lo; p[4 + t] = hi;
        }
    } else {
#pragma unroll
        for (int t = 0; t < 4; t++) {
            float2 lo = q[t], hi = q[4 + t];
            p[2*t]     = make_float2((lo.x + hi.x) * RS2, (lo.x - hi.x) * RS2);
            p[2*t + 1] = make_float2((lo.y + hi.y) * RS2, (lo.y - hi.y) * RS2);
        }
    }
}
template<bool FWD>
__device__ __forceinline__ void scr_h(float2* S2, int tid) {
    if (tid < 128) {
        int d = tid >> 3, wp = tid & 7;
        line_f2<16, SSH2, FWD>(S2 + d * SSD2 + wp);
    }
}
template<bool FWD>
__device__ __forceinline__ void scr_d(float2* S2, int tid) {
    if (tid < 128) {
        int h = tid >> 3, wp = tid & 7;
        line_f2<16, SSD2, FWD>(S2 + h * SSH2 + wp);
    }
}

// ---- 2D Haar pyramid fwd + soft-threshold + inv on v[64] in registers ----
__device__ __forceinline__ void pyramid(float* v) {
#pragma unroll
    for (int lev = 0; lev < 3; lev++) {
        const int S = 8 >> lev, H = S >> 1;
#pragma unroll
        for (int j = 0; j < S; j++) {
            float t[4], u[4];
#pragma unroll
            for (int i = 0; i < H; i++) {
                float a = v[(2*i)*8+j], b = v[(2*i+1)*8+j];
                t[i] = (a + b) * RS2; u[i] = (a - b) * RS2;
            }
#pragma unroll
            for (int i = 0; i < H; i++) { v[i*8+j] = t[i]; v[(i+H)*8+j] = u[i]; }
        }
#pragma unroll
        for (int i = 0; i < S; i++) {
            float t[4], u[4];
#pragma unroll
            for (int j = 0; j < H; j++) {
                float a = v[i*8+2*j], b = v[i*8+2*j+1];
                t[j] = (a + b) * RS2; u[j] = (a - b) * RS2;
            }
#pragma unroll
            for (int j = 0; j < H; j++) { v[i*8+j] = t[j]; v[i*8+j+H] = u[j]; }
        }
    }
#pragma unroll
    for (int e = 1; e < 64; e++)
        v[e] = v[e] - fminf(fmaxf(v[e], -TAU_V), TAU_V);
#pragma unroll
    for (int lev = 2; lev >= 0; lev--) {
        const int S = 8 >> lev, H = S >> 1;
#pragma unroll
        for (int i = 0; i < S; i++) {
            float t[4], u[4];
#pragma unroll
            for (int j = 0; j < H; j++) {
                float lo = v[i*8+j], hi = v[i*8+j+H];
                t[j] = (lo + hi) * RS2; u[j] = (lo - hi) * RS2;
            }
#pragma unroll
            for (int j = 0; j < H; j++) { v[i*8+2*j] = t[j]; v[i*8+2*j+1] = u[j]; }
        }
#pragma unroll
        for (int j = 0; j < S; j++) {
            float t[4], u[4];
#pragma unroll
            for (int i = 0; i < H; i++) {
                float lo = v[i*8+j], hi = v[(i+H)*8+j];
                t[i] = (lo + hi) * RS2; u[i] = (lo - hi) * RS2;
            }
#pragma unroll
            for (int i = 0; i < H; i++) { v[(2*i)*8+j] = t[i]; v[(2*i+1)*8+j] = u[i]; }
        }
    }
}

// ---- level-1 bandlet phase: blocks are d-interleaved (slot = 2*band_d + p) ----
__device__ void bandlet_L1(float* T, float2* T2, int tid, int base, int count) {
    const int nrm = tid >> 6;                 // warp-uniform
    const int idx = tid & 63;
    const bool active = (nrm < 3) && (idx < count * 8);
    const int s = idx & 7;
    int p = 0, bh = 0, bw = 0;
    if (active) {
        int e = BTAB[base + (idx >> 3)];
        p = e >> 4; bh = ((e >> 2) & 3) * 8; bw = (e & 3) * 8;
    }
    float v[64];
    if (active) {
        if (nrm == 0) {
            const float2* q = T2 + (2*s + p)*SD2 + bh*SH2 + (bw >> 1);
#pragma unroll
            for (int i = 0; i < 8; i++)
#pragma unroll
                for (int jp = 0; jp < 4; jp++) {
                    float2 r = q[i*SH2 + jp];
                    v[i*8 + 2*jp] = r.x; v[i*8 + 2*jp + 1] = r.y;
                }
        } else if (nrm == 1) {
            const float2* q = T2 + p*SD2 + (bh+s)*SH2 + (bw >> 1);
#pragma unroll
            for (int i = 0; i < 8; i++)
#pragma unroll
                for (int jp = 0; jp < 4; jp++) {
                    float2 r = q[i*2*SD2 + jp];
                    v[i*8 + 2*jp] = r.x; v[i*8 + 2*jp + 1] = r.y;
                }
        } else {
            const float* q = T + p*SD + bh*SH + bw + s;
#pragma unroll
            for (int i = 0; i < 8; i++)
#pragma unroll
                for (int j = 0; j < 8; j++) v[i*8+j] = q[i*2*SD + j*SH];
        }
        pyramid(v);
    }
    __syncthreads();
    if (active && nrm == 0) {
        float2* q = T2 + (2*s + p)*SD2 + bh*SH2 + (bw >> 1);
#pragma unroll
        for (int i = 0; i < 8; i++)
#pragma unroll
            for (int jp = 0; jp < 4; jp++)
                q[i*SH2 + jp] = make_float2(v[i*8 + 2*jp], v[i*8 + 2*jp + 1]);
    }
    __syncthreads();
    if (active && nrm == 1) {
        float2* q = T2 + p*SD2 + (bh+s)*SH2 + (bw >> 1);
#pragma unroll
        for (int i = 0; i < 8; i++)
#pragma unroll
            for (int jp = 0; jp < 4; jp++) {
                float2 r = q[i*2*SD2 + jp];
                r.x += v[i*8 + 2*jp]; r.y += v[i*8 + 2*jp + 1];
                q[i*2*SD2 + jp] = r;
            }
    }
    __syncthreads();
    if (active && nrm == 2) {
        float* q = T + p*SD + bh*SH + bw + s;
#pragma unroll
        for (int i = 0; i < 8; i++)
#pragma unroll
            for (int j = 0; j < 8; j++)
                q[i*2*SD + j*SH] = (q[i*2*SD + j*SH] + v[i*8+j]) * (1.0f / 3.0f);
    }
    // no trailing barrier: next phase's blocks are disjoint
}

// ---- level-2 bandlet in compact scratch: 7 blocks, one phase ----
__device__ void bandlet_L2(float* SC, float2* S2, int tid) {
    const int nrm = tid >> 6;
    const int idx = tid & 63;
    const bool active = (nrm < 3) && (idx < 56);
    const int s = idx & 7;
    int bd = 0, bh = 0, bw = 0;
    if (active) {
        int slot = (idx >> 3) + 1;
        bd = ((slot >> 2) & 1) * 8; bh = ((slot >> 1) & 1) * 8; bw = (slot & 1) * 8;
    }
    float v[64];
    if (active) {
        if (nrm == 0) {
            const float2* q = S2 + (bd+s)*SSD2 + bh*SSH2 + (bw >> 1);
#pragma unroll
            for (int i = 0; i < 8; i++)
#pragma unroll
                for (int jp = 0; jp < 4; jp++) {
                    float2 r = q[i*SSH2 + jp];
                    v[i*8 + 2*jp] = r.x; v[i*8 + 2*jp + 1] = r.y;
                }
        } else if (nrm == 1) {
            const float2* q = S2 + bd*SSD2 + (bh+s)*SSH2 + (bw >> 1);
#pragma unroll
            for (int i = 0; i < 8; i++)
#pragma unroll
                for (int jp = 0; jp < 4; jp++) {
                    float2 r = q[i*SSD2 + jp];
                    v[i*8 + 2*jp] = r.x; v[i*8 + 2*jp + 1] = r.y;
                }
        } else {
            const float* q = SC + bd*SSD + bh*SSH + bw + s;
#pragma unroll
            for (int i = 0; i < 8; i++)
#pragma unroll
                for (int j = 0; j < 8; j++) v[i*8+j] = q[i*SSD + j*SSH];
        }
        pyramid(v);
    }
    __syncthreads();
    if (active && nrm == 0) {
        float2* q = S2 + (bd+s)*SSD2 + bh*SSH2 + (bw >> 1);
#pragma unroll
        for (int i = 0; i < 8; i++)
#pragma unroll
            for (int jp = 0; jp < 4; jp++)
                q[i*SSH2 + jp] = make_float2(v[i*8 + 2*jp], v[i*8 + 2*jp + 1]);
    }
    __syncthreads();
    if (active && nrm == 1) {
        float2* q = S2 + bd*SSD2 + (bh+s)*SSH2 + (bw >> 1);
#pragma unroll
        for (int i = 0; i < 8; i++)
#pragma unroll
            for (int jp = 0; jp < 4; jp++) {
                float2 r = q[i*SSD2 + jp];
                r.x += v[i*8 + 2*jp]; r.y += v[i*8 + 2*jp + 1];
                q[i*SSD2 + jp] = r;
            }
    }
    __syncthreads();
    if (active && nrm == 2) {
        float* q = SC + bd*SSD + bh*SSH + bw + s;
#pragma unroll
        for (int i = 0; i < 8; i++)
#pragma unroll
            for (int j = 0; j < 8; j++)
                q[i*SSD + j*SSH] = (q[i*SSD + j*SSH] + v[i*8+j]) * (1.0f / 3.0f);
    }
}

__global__ __launch_bounds__(NT, 2) __cluster_dims__(2, 1, 1)
void bandlet3d_kernel(const float* __restrict__ x, float* __restrict__ y) {
    float2* T2 = smem2;                       // 16 d-slots of the tile (this CTA's half)
    float*  T  = reinterpret_cast<float*>(smem2);
    float2* S2 = smem2 + HALF_F2;             // compact 16^3 lll scratch
    float*  SC = reinterpret_cast<float*>(S2);
    const int tid = threadIdx.x;
    const int bid = blockIdx.x;
    const uint32_t rho = bid & 1;             // rank in cluster (d-half)
    const int c = bid >> 1;                   // tile index

    const int batch = c / 125;
    const int rem = c - batch * 125;
    const int td = rem / 25;
    const int th = (rem / 5) % 5;
    const int tw = rem % 5;
    const long long gb = (long long)batch * 4096000LL
                       + (long long)(td * 32 + 16 * (int)rho) * 25600LL
                       + th * 32 * 160 + tw * 32;

    // ---- fused coalesced load + level-1 w-transform (this CTA's 16 d-slices) ----
    for (int l = tid; l < 4096; l += NT) {
        int w4 = l & 7, h = (l >> 3) & 31, dl = l >> 8;
        float4 q = *reinterpret_cast<const float4*>(x + gb + dl*25600 + h*160 + w4*4);
        float2* p = T2 + dl*SD2 + h*SH2;
        p[w4]     = make_float2((q.x + q.y) * RS2, (q.z + q.w) * RS2);
        p[w4 + 8] = make_float2((q.x - q.y) * RS2, (q.z - q.w) * RS2);
    }
    __syncthreads();

    // forward level-1 h (compacted), then level-1 d (interleaved, fully local)
    { int slot = tid >> 4, wp = tid & 15; line_f2<32, SH2, true>(T2 + slot*SD2 + wp); }
    __syncthreads();
    dpassD(T2, tid);

    cluster_sync();   // peer's lo-d (even slots) final before gather

    // ---- gather full 16^3 lll into scratch (own half local, peer half via DSMEM) ----
    {
        const uint32_t t2u = smem_u32(T2);
        for (int m = tid; m < 2048; m += NT) {
            int wp = m & 7, h = (m >> 3) & 15, d2 = m >> 7;   // d2 = global lll d index
            int k = d2 & 7;
            int src2 = k * 2 * SD2 + h * SH2 + wp;            // local slot 2k
            float2 val = ((uint32_t)(d2 >> 3) == rho) ? T2[src2]
                                                      : peer_ld_f2(t2u + src2 * 8, rho ^ 1u);
            S2[d2 * SSD2 + h * SSH2 + wp] = val;
        }
    }
    __syncthreads();

    // ---- level-1 bandlet: this CTA's 28 blocks in 4 phases (8,8,8,4) ----
    bandlet_L1(T, T2, tid, 0, 8);
    bandlet_L1(T, T2, tid, 8, 8);
    bandlet_L1(T, T2, tid, 16, 8);
    bandlet_L1(T, T2, tid, 24, 4);
    // no barrier needed: L2 subtree below touches only scratch (disjoint from T)

    // ---- level-2 subtree in scratch (redundant in both CTAs — keeps them symmetric) ----
    scr_w<true>(S2, tid);   __syncthreads();
    scr_h<true>(S2, tid);   __syncthreads();
    scr_d<true>(S2, tid);   __syncthreads();
    bandlet_L2(SC, S2, tid);
    __syncthreads();
    scr_d<false>(S2, tid);  __syncthreads();
    scr_h<false>(S2, tid);  __syncthreads();
    scr_w<false>(S2, tid);

    cluster_sync();   // peer's gather long done -> safe to overwrite own lll slots

    // ---- scatter own half of reconstructed lll back into T (local only) ----
    for (int m = tid; m < 1024; m += NT) {
        int wp = m & 7, h = (m >> 3) & 15, k = m >> 7;
        T2[k * 2 * SD2 + h * SH2 + wp] = S2[(8 * (int)rho + k) * SSD2 + h * SSH2 + wp];
    }
    __syncthreads();

    // inverse level-1 d (same interleaved butterfly), h, then w fused with store
    dpassD(T2, tid);
    __syncthreads();
    { int slot = tid >> 4, wp = tid & 15; line_f2<32, SH2, false>(T2 + slot*SD2 + wp); }
    __syncthreads();

    for (int l = tid; l < 4096; l += NT) {
        int w4 = l & 7, h = (l >> 3) & 31, dl = l >> 8;
        const float2* p = T2 + dl*SD2 + h*SH2;
        float2 lo = p[w4], hi = p[w4 + 8];
        float4 q;
        q.x = (lo.x + hi.x) * RS2; q.y = (lo.x - hi.x) * RS2;
        q.z = (lo.y + hi.y) * RS2; q.w = (lo.y - hi.y) * RS2;
        *reinterpret_cast<float4*>(y + gb + dl*25600 + h*160 + w4*4) = q;
    }
}

extern "C" void kernel_launch(void* const* d_in, const int* in_sizes, int n_in,
                              void* d_out, int out_size) {
    const float* x = (const float*)d_in[0];
    float* y = (float*)d_out;
    (void)in_sizes; (void)n_in; (void)out_size;

    const size_t smem_bytes = (size_t)(HALF_F2 + SCR_F2) * sizeof(float2); // 88320 B
    cudaFuncSetAttribute(bandlet3d_kernel,
                         cudaFuncAttributeMaxDynamicSharedMemorySize, (int)smem_bytes);
    bandlet3d_kernel<<<500, NT, smem_bytes>>>(x, y);
}